// round 14
// baseline (speedup 1.0000x reference)
#include <cuda_runtime.h>
#include <cuda_bf16.h>

#define NPTS 200000
#define NBOX 128
#define NSAMP 256
#define NANCH 3
#define LCAP 768           // per-box member list capacity (max expected ~420)
#define NCELL 32           // 32x32 cells of 4.8 m over [-75.2, ...)

// Scratch (no cudaMalloc allowed). BSS-zero at module load; k_tail's last
// block restores g_inter/g_cnt/g_done to zero each run => replay-safe.
__device__ int      g_inter[NBOX * NBOX];                // pairwise intersection counts
__device__ int      g_cnt[NBOX];                         // member-list counts
__device__ int      g_done;                              // k_tail arrival counter
__device__ int      g_list[NBOX][LCAP];                  // member point indices
__device__ __align__(16) uint4 g_listm[NBOX][LCAP];      // member's 128-bit box mask

// ---------------------------------------------------------------------------
// K1: points. Each block redundantly computes box params + interval masks in
//     smem (no separate setup kernel), then processes its 256 points.
// ---------------------------------------------------------------------------
__global__ void __launch_bounds__(256) k_points(const float* __restrict__ pts,
                                                const float* __restrict__ boxes)
{
    __shared__ float4 sv[NBOX];      // qx, qy, rad_vox
    __shared__ float4 sc[NBOX];      // cx, cy, thresh
    __shared__ int4   srect[NBOX];   // xlo, xhi, ylo, yhi (cell units, unclamped)
    __shared__ uint4  scol[NCELL], srow[NCELL];  // interval masks

    int tid = threadIdx.x;
    if (tid < NBOX) {
        int m = tid;
        float cx = boxes[m * 7 + 0], cy = boxes[m * 7 + 1];
        float hx = __fmul_rn(boxes[m * 7 + 3], 0.5f);
        float hy = __fmul_rn(boxes[m * 7 + 4], 0.5f);
        float r  = __fsqrt_rn(__fadd_rn(__fmul_rn(hx, hx), __fmul_rn(hy, hy)));
        float rv = ceilf(__fdiv_rn(r, 0.4f));
        float qx = floorf(__fdiv_rn(__fsub_rn(cx, -75.2f), 0.4f));
        float qy = floorf(__fdiv_rn(__fsub_rn(cy, -75.2f), 0.4f));
        // largest s with sqrt_rn(s) <= r  (exact replacement for per-point sqrt)
        float t = __fmul_rn(r, r);
        while (__fsqrt_rn(t) > r) t = __uint_as_float(__float_as_uint(t) - 1u);
        for (;;) {
            float t2 = __uint_as_float(__float_as_uint(t) + 1u);
            if (__fsqrt_rn(t2) <= r) t = t2; else break;
        }
        sv[m] = make_float4(qx, qy, rv, 0.f);
        sc[m] = make_float4(cx, cy, t, 0.f);
        // conservative influence radius covers voxel AND circle predicates
        float R = (rv + 1.0f) * 0.4f + 0.01f;
        srect[m] = make_int4((int)floorf((cx - R + 75.2f) / 4.8f),
                             (int)floorf((cx + R + 75.2f) / 4.8f),
                             (int)floorf((cy - R + 75.2f) / 4.8f),
                             (int)floorf((cy + R + 75.2f) / 4.8f));
    }
    __syncthreads();
    {
        // 256 threads = (col|row) x 32 cells x 4 words
        int isrow = tid >> 7;
        int c     = (tid >> 2) & 31;
        int wsel  = tid & 3;
        unsigned m = 0;
        #pragma unroll
        for (int k = 0; k < 32; k++) {
            int4 rc = srect[wsel * 32 + k];
            int lo = isrow ? rc.z : rc.x;
            int hi = isrow ? rc.w : rc.y;
            if (c >= lo && c <= hi) m |= 1u << k;
        }
        ((unsigned*)(isrow ? srow : scol))[c * 4 + wsel] = m;
    }
    __syncthreads();

    int n = blockIdx.x * 256 + tid;
    if (n >= NPTS) return;
    float x = __ldg(&pts[n * 5 + 0]), y = __ldg(&pts[n * 5 + 1]);
    float c0 = floorf(__fdiv_rn(__fsub_rn(x, -75.2f), 0.4f));
    float c1 = floorf(__fdiv_rn(__fsub_rn(y, -75.2f), 0.4f));

    int cxi = (int)floorf(__fdiv_rn(__fsub_rn(x, -75.2f), 4.8f));
    int cyi = (int)floorf(__fdiv_rn(__fsub_rn(y, -75.2f), 4.8f));
    cxi = cxi < 0 ? 0 : (cxi > NCELL - 1 ? NCELL - 1 : cxi);
    cyi = cyi < 0 ? 0 : (cyi > NCELL - 1 ? NCELL - 1 : cyi);
    uint4 ca = scol[cxi], ra = srow[cyi];
    unsigned mw[4] = {ca.x & ra.x, ca.y & ra.y, ca.z & ra.z, ca.w & ra.w};

    bool vm = false;
    unsigned memb[4] = {0u, 0u, 0u, 0u};
    #pragma unroll
    for (int wm = 0; wm < 4; wm++) {
        unsigned b = mw[wm];
        while (b) {
            int l = __ffs(b) - 1; b &= b - 1;
            int m = wm * 32 + l;
            float4 v = sv[m];
            vm |= (fabsf(__fsub_rn(v.x, c0)) < v.z) && (fabsf(__fsub_rn(v.y, c1)) < v.z);
            float4 c = sc[m];
            float dx = __fsub_rn(x, c.x), dy = __fsub_rn(y, c.y);
            float s = __fadd_rn(__fmul_rn(dx, dx), __fmul_rn(dy, dy));
            if (s <= c.z) memb[wm] |= 1u << l;
        }
    }
    if (!vm) return;
    if (!(memb[0] | memb[1] | memb[2] | memb[3])) return;

    uint4 mv = make_uint4(memb[0], memb[1], memb[2], memb[3]);
    #pragma unroll
    for (int wm = 0; wm < 4; wm++) {
        unsigned b = memb[wm];
        while (b) {
            int l = __ffs(b) - 1; b &= b - 1;
            int i = wm * 32 + l;
            int pos = atomicAdd(&g_cnt[i], 1);
            if (pos < LCAP) { g_list[i][pos] = n; g_listm[i][pos] = mv; }
            #pragma unroll
            for (int wj = 0; wj < 4; wj++) {
                unsigned bb = memb[wj];
                while (bb) {
                    int l2 = __ffs(bb) - 1; bb &= bb - 1;
                    int j = wj * 32 + l2;
                    atomicAdd(&g_inter[i * NBOX + j], 1);
                }
            }
        }
    }
}

// ---------------------------------------------------------------------------
// K2: 128 blocks; every block redundantly recomputes the group phase from
//     g_inter, stashes its g_cnt needs, then ARRIVES on g_done. The single
//     last arriver (no one waits) restores g_inter/g_cnt/g_done to zero for
//     the next graph replay. Then each block samples its own group.
// ---------------------------------------------------------------------------
__global__ void __launch_bounds__(1024) k_tail(const float* __restrict__ pts,
                                               const int* __restrict__ labels,
                                               float* __restrict__ out,
                                               float* __restrict__ out_anchor,
                                               int write_anchor)
{
    // group-phase shared state
    __shared__ int s_lab[NBOX], s_diag[NBOX], s_idx[NBOX], s_flagg[NBOX];
    __shared__ unsigned s_candm[4], s_joinm[4];
    __shared__ int s_jointg[NBOX], s_addcnt[NBOX];
    __shared__ int s_aidx[NBOX * NANCH];
    __shared__ int s_cnts[NANCH];
    __shared__ int s_last;
    // sample-phase shared state (per-class key arrays)
    __shared__ unsigned sk3[LCAP], sk2[2 * LCAP], sk1[3 * LCAP];
    __shared__ int sidx[NSAMP];
    __shared__ int s_n3, s_n2, s_n1;

    int tid = threadIdx.x, lane = tid & 31, w = tid >> 5;
    int g = blockIdx.x;

    // ================= group phase (redundant in every block) =================
    if (tid < NBOX) {
        s_lab[tid]  = labels[tid];
        s_diag[tid] = g_inter[tid * NBOX + tid];
        s_jointg[tid] = -1;
        s_addcnt[tid] = 0;
    }
    for (int t = tid; t < NBOX * NANCH; t += 1024) s_aidx[t] = -1;
    if (tid == 0) { s_n3 = 0; s_n2 = 0; s_n1 = 0; s_last = 0; }
    __syncthreads();

    #pragma unroll
    for (int rr = 0; rr < 4; rr++) {
        int i = w * 4 + rr;
        int li = s_lab[i], ci = s_diag[i];
        float best = -1.f; int bidx = 0;
        #pragma unroll
        for (int jj = 0; jj < 4; jj++) {
            int j = lane + jj * 32;
            float v = 0.f;
            if (j != i && s_lab[j] == li) {
                int in_ = g_inter[i * NBOX + j];
                int un  = ci + s_diag[j] - in_;
                if (un > 0) v = __fdiv_rn((float)in_, (float)un);
            }
            if (v > best) { best = v; bidx = j; }
        }
        #pragma unroll
        for (int o = 16; o; o >>= 1) {
            float v2 = __shfl_down_sync(0xffffffffu, best, o);
            int  b2  = __shfl_down_sync(0xffffffffu, bidx, o);
            if (v2 > best || (v2 == best && b2 < bidx)) { best = v2; bidx = b2; }
        }
        if (lane == 0) { s_idx[i] = bidx; s_flagg[i] = (best > 0.5f) ? 1 : 0; }
    }
    __syncthreads();
    if (tid < NBOX) {
        unsigned m = __ballot_sync(0xffffffffu, s_flagg[tid]);
        if (lane == 0) s_candm[w] = m;
    }
    __syncthreads();

    if (tid == 0) {
        unsigned jm0 = 0, jm1 = 0, jm2 = 0, jm3 = 0;
        #pragma unroll
        for (int wi = 0; wi < 4; wi++) {
            unsigned bm = s_candm[wi];
            while (bm) {
                int b = __ffs(bm) - 1; bm &= bm - 1;
                int ii = wi * 32 + b;
                int j = s_idx[ii];
                int gj = -1;
                if (j < ii) {
                    int jt = s_jointg[j];
                    if (jt >= 0) gj = jt;
                    else {
                        int jw = j >> 5, jb2 = j & 31;
                        unsigned sel = (jw == 0) ? jm0 : (jw == 1) ? jm1 : (jw == 2) ? jm2 : jm3;
                        int jb = __popc(sel & ((jb2 == 0) ? 0u : (0xffffffffu >> (32 - jb2))));
                        if (jw > 0) jb += __popc(jm0);
                        if (jw > 1) jb += __popc(jm1);
                        if (jw > 2) jb += __popc(jm2);
                        gj = j - jb;       // leader j's group id
                    }
                }
                if (gj >= 0 && s_addcnt[gj] < 2) {   // gcnt[gj] = 1 + addcnt < 3
                    int ts = 1 + s_addcnt[gj];
                    s_addcnt[gj] = ts;
                    s_jointg[ii] = gj;
                    s_aidx[gj * NANCH + ts] = ii;
                    if (wi == 0) jm0 |= 1u << b;
                    else if (wi == 1) jm1 |= 1u << b;
                    else if (wi == 2) jm2 |= 1u << b;
                    else jm3 |= 1u << b;
                }
            }
        }
        s_joinm[0] = jm0; s_joinm[1] = jm1; s_joinm[2] = jm2; s_joinm[3] = jm3;
    }
    __syncthreads();

    if (tid < NBOX) {
        int ii = tid;
        unsigned jmw = s_joinm[ii >> 5];
        if (!((jmw >> (ii & 31)) & 1u)) {
            int b2 = ii & 31;
            int jb = __popc(jmw & ((b2 == 0) ? 0u : (0xffffffffu >> (32 - b2))));
            if (ii >= 32)  jb += __popc(s_joinm[0]);
            if (ii >= 64)  jb += __popc(s_joinm[1]);
            if (ii >= 96)  jb += __popc(s_joinm[2]);
            s_aidx[(ii - jb) * NANCH + 0] = ii;
        }
    }
    __syncthreads();

    // ---- stash own g_cnt needs BEFORE arrival (zeroer may clear g_cnt) ----
    int a[3];
    a[0] = s_aidx[g * NANCH + 0];
    a[1] = s_aidx[g * NANCH + 1];
    a[2] = s_aidx[g * NANCH + 2];
    if (tid < NANCH) {
        int ak = s_aidx[g * NANCH + tid];
        s_cnts[tid] = (ak >= 0) ? g_cnt[ak] : 0;
    }
    __syncthreads();   // all g_inter + g_cnt reads of this block are complete

    // ---- arrival: last block (and only it) restores global state to zero ----
    if (tid == 0) {
        __threadfence();
        int old = atomicAdd(&g_done, 1);
        if (old == NBOX - 1) s_last = 1;
    }
    __syncthreads();
    if (s_last) {
        for (int t = tid; t < NBOX * NBOX; t += 1024) g_inter[t] = 0;
        if (tid < NBOX) g_cnt[tid] = 0;
        __syncthreads();
        if (tid == 0) { __threadfence(); g_done = 0; }
    }

    if (g == 0 && write_anchor && tid < NBOX) {
        #pragma unroll
        for (int k = 0; k < NANCH; k++)
            out_anchor[tid * NANCH + k] = (float)s_aidx[tid * NANCH + k];
    }

    // ================= sample phase (own group) =================
    float* orow = out + (size_t)g * NSAMP * 5;
    if (a[0] < 0) {
        for (int k = tid; k < NSAMP * 5; k += 1024) orow[k] = 0.f;
        return;
    }
    int nv = (a[1] < 0) ? 1 : ((a[2] < 0) ? 2 : 3);

    for (int k = 0; k < nv; k++) {
        int cnt = s_cnts[k];
        if (cnt > LCAP) cnt = LCAP;
        for (int e = tid; e < cnt; e += 1024) {
            int p = g_list[a[k]][e];
            uint4 mv = g_listm[a[k]][e];
            unsigned mm[4] = {mv.x, mv.y, mv.z, mv.w};
            bool dup = false;
            int cls = 1;
            #pragma unroll
            for (int j = 0; j < 3; j++) {
                if (j < nv && j != k) {
                    unsigned in = (mm[a[j] >> 5] >> (a[j] & 31)) & 1u;
                    if (in) { cls++; if (j < k) dup = true; }
                }
            }
            if (!dup) {
                if (cls == 3)      sk3[atomicAdd(&s_n3, 1)] = (unsigned)p;
                else if (cls == 2) sk2[atomicAdd(&s_n2, 1)] = (unsigned)p;
                else               sk1[atomicAdd(&s_n1, 1)] = (unsigned)p;
            }
        }
    }
    __syncthreads();
    int n3 = s_n3, n2 = s_n2, n1 = s_n1;

    // class 3 (base 0), class 2 (base n3), class 1 (base n3+n2); idx ascending
    for (int i = tid; i < n3; i += 1024) {
        unsigned my = sk3[i];
        int r = 0;
        for (int j = 0; j < n3; j++) r += (sk3[j] < my);
        if (r < NSAMP) sidx[r] = (int)my;
    }
    if (n3 < NSAMP) {
        for (int i = tid; i < n2; i += 1024) {
            unsigned my = sk2[i];
            int r = 0;
            for (int j = 0; j < n2; j++) r += (sk2[j] < my);
            int pos = n3 + r;
            if (pos < NSAMP) sidx[pos] = (int)my;
        }
    }
    if (n3 + n2 < NSAMP) {
        for (int i = tid; i < n1; i += 1024) {
            unsigned my = sk1[i];
            int r = 0;
            for (int j = 0; j < n1; j++) r += (sk1[j] < my);
            int pos = n3 + n2 + r;
            if (pos < NSAMP) sidx[pos] = (int)my;
        }
    }
    __syncthreads();
    int total = n3 + n2 + n1;
    int filled = total < NSAMP ? total : NSAMP;
    for (int k = tid; k < NSAMP * 5; k += 1024) {
        int s = k / 5, f = k - s * 5;
        orow[k] = (s < filled) ? pts[(size_t)sidx[s] * 5 + f] : 0.f;
    }
}

// ---------------------------------------------------------------------------
extern "C" void kernel_launch(void* const* d_in, const int* in_sizes, int n_in,
                              void* d_out, int out_size)
{
    const float* pts    = (const float*)d_in[0];
    const float* boxes  = (const float*)d_in[1];
    const int*   labels = (const int*)d_in[2];
    float* out = (float*)d_out;

    const int sampled_elems = NBOX * NSAMP * 5;
    int write_anchor = (out_size >= sampled_elems + NBOX * NANCH) ? 1 : 0;
    float* out_anchor = out + sampled_elems;

    k_points<<<(NPTS + 255) / 256, 256>>>(pts, boxes);
    k_tail<<<NBOX, 1024>>>(pts, labels, out, out_anchor, write_anchor);
}

// round 15
// speedup vs baseline: 1.2485x; 1.2485x over previous
#include <cuda_runtime.h>
#include <cuda_bf16.h>

#define NPTS 200000
#define NBOX 128
#define NSAMP 256
#define NANCH 3
#define LCAP 768           // per-box member list capacity (max expected ~420)
#define NCELL 32           // 32x32 cells of 4.8 m over [-75.2, ...)

// Scratch (no cudaMalloc allowed)
__device__ int      g_inter[NBOX * NBOX];                // pairwise intersection counts
__device__ int      g_cnt[NBOX];                         // member-list counts
__device__ int      g_list[NBOX][LCAP];                  // member point indices
__device__ __align__(16) uint4 g_listm[NBOX][LCAP];      // member's 128-bit box mask
__device__ __align__(16) float4 g_vox[NBOX];             // qx, qy, rad_vox, -
__device__ __align__(16) float4 g_cir[NBOX];             // cx, cy, thresh, -
__device__ __align__(16) unsigned g_cellmask[NCELL * NCELL][4]; // per-cell box mask

// ---------------------------------------------------------------------------
// K1: 9 blocks. Blocks 0-7: zero g_inter slices (+g_cnt in block 0).
//     Block 8: zero cellmask, then box params + cellmask build.
// ---------------------------------------------------------------------------
__global__ void __launch_bounds__(1024) k_setup(const float* __restrict__ boxes)
{
    int tid = threadIdx.x;
    int b = blockIdx.x;
    if (b < 8) {
        // zero 2048 ints of g_inter each
        int base = b * 2048;
        ((int*)g_inter)[base + tid] = 0;
        ((int*)g_inter)[base + 1024 + tid] = 0;
        if (b == 0 && tid < NBOX) g_cnt[tid] = 0;
        return;
    }
    // block 8: cellmask + params
    for (int i = tid; i < NCELL * NCELL * 4; i += 1024) ((unsigned*)g_cellmask)[i] = 0u;
    __syncthreads();
    if (tid < NBOX) {
        int m = tid;
        float cx = boxes[m * 7 + 0], cy = boxes[m * 7 + 1];
        float hx = __fmul_rn(boxes[m * 7 + 3], 0.5f);
        float hy = __fmul_rn(boxes[m * 7 + 4], 0.5f);
        float r  = __fsqrt_rn(__fadd_rn(__fmul_rn(hx, hx), __fmul_rn(hy, hy)));
        float rv = ceilf(__fdiv_rn(r, 0.4f));
        float qx = floorf(__fdiv_rn(__fsub_rn(cx, -75.2f), 0.4f));
        float qy = floorf(__fdiv_rn(__fsub_rn(cy, -75.2f), 0.4f));
        // largest s with sqrt_rn(s) <= r  (exact replacement for per-point sqrt)
        float t = __fmul_rn(r, r);
        while (__fsqrt_rn(t) > r) t = __uint_as_float(__float_as_uint(t) - 1u);
        for (;;) {
            float t2 = __uint_as_float(__float_as_uint(t) + 1u);
            if (__fsqrt_rn(t2) <= r) t = t2; else break;
        }
        g_vox[m] = make_float4(qx, qy, rv, 0.f);
        g_cir[m] = make_float4(cx, cy, t, 0.f);

        // conservative influence radius covers voxel AND circle predicates
        float R = (rv + 1.0f) * 0.4f + 0.01f;
        int xlo = (int)floorf((cx - R + 75.2f) / 4.8f);
        int xhi = (int)floorf((cx + R + 75.2f) / 4.8f);
        int ylo = (int)floorf((cy - R + 75.2f) / 4.8f);
        int yhi = (int)floorf((cy + R + 75.2f) / 4.8f);
        xlo = xlo < 0 ? 0 : xlo;  ylo = ylo < 0 ? 0 : ylo;
        xhi = xhi > NCELL - 1 ? NCELL - 1 : xhi;
        yhi = yhi > NCELL - 1 ? NCELL - 1 : yhi;
        for (int cyi = ylo; cyi <= yhi; cyi++)
            for (int cxi = xlo; cxi <= xhi; cxi++)
                atomicOr(&g_cellmask[cyi * NCELL + cxi][m >> 5], 1u << (m & 31));
    }
}

// ---------------------------------------------------------------------------
// K2: per point, test only candidate boxes from the cell mask.
//     Writes member lists (index + full membership mask) and inter counts.
// ---------------------------------------------------------------------------
__global__ void __launch_bounds__(256) k_points(const float* __restrict__ pts)
{
    int n = blockIdx.x * 256 + threadIdx.x;
    if (n >= NPTS) return;
    float x = __ldg(&pts[n * 5 + 0]), y = __ldg(&pts[n * 5 + 1]);
    float c0 = floorf(__fdiv_rn(__fsub_rn(x, -75.2f), 0.4f));
    float c1 = floorf(__fdiv_rn(__fsub_rn(y, -75.2f), 0.4f));

    int cxi = (int)floorf(__fdiv_rn(__fsub_rn(x, -75.2f), 4.8f));
    int cyi = (int)floorf(__fdiv_rn(__fsub_rn(y, -75.2f), 4.8f));
    cxi = cxi < 0 ? 0 : (cxi > NCELL - 1 ? NCELL - 1 : cxi);
    cyi = cyi < 0 ? 0 : (cyi > NCELL - 1 ? NCELL - 1 : cyi);
    uint4 cm = __ldg((const uint4*)&g_cellmask[cyi * NCELL + cxi][0]);
    unsigned mw[4] = {cm.x, cm.y, cm.z, cm.w};

    bool vm = false;
    unsigned memb[4] = {0u, 0u, 0u, 0u};
    #pragma unroll
    for (int wm = 0; wm < 4; wm++) {
        unsigned b = mw[wm];
        while (b) {
            int l = __ffs(b) - 1; b &= b - 1;
            int m = wm * 32 + l;
            float4 v = __ldg(&g_vox[m]);
            vm |= (fabsf(__fsub_rn(v.x, c0)) < v.z) && (fabsf(__fsub_rn(v.y, c1)) < v.z);
            float4 c = __ldg(&g_cir[m]);
            float dx = __fsub_rn(x, c.x), dy = __fsub_rn(y, c.y);
            float s = __fadd_rn(__fmul_rn(dx, dx), __fmul_rn(dy, dy));
            if (s <= c.z) memb[wm] |= 1u << l;
        }
    }
    if (!vm) return;
    if (!(memb[0] | memb[1] | memb[2] | memb[3])) return;

    uint4 mv = make_uint4(memb[0], memb[1], memb[2], memb[3]);
    #pragma unroll
    for (int wm = 0; wm < 4; wm++) {
        unsigned b = memb[wm];
        while (b) {
            int l = __ffs(b) - 1; b &= b - 1;
            int i = wm * 32 + l;
            int pos = atomicAdd(&g_cnt[i], 1);
            if (pos < LCAP) { g_list[i][pos] = n; g_listm[i][pos] = mv; }
            #pragma unroll
            for (int wj = 0; wj < 4; wj++) {
                unsigned bb = memb[wj];
                while (bb) {
                    int l2 = __ffs(bb) - 1; bb &= bb - 1;
                    int j = wj * 32 + l2;
                    atomicAdd(&g_inter[i * NBOX + j], 1);
                }
            }
        }
    }
}

// ---------------------------------------------------------------------------
// K3: 128 blocks; EVERY block redundantly recomputes the group phase from
//     g_inter (deterministic, L2-hot) -> no inter-block sync at all.
//     Then each block samples its own group via per-class rank-scatter.
// ---------------------------------------------------------------------------
__global__ void __launch_bounds__(1024) k_tail(const float* __restrict__ pts,
                                               const int* __restrict__ labels,
                                               float* __restrict__ out,
                                               float* __restrict__ out_anchor,
                                               int write_anchor)
{
    // group-phase shared state
    __shared__ int s_lab[NBOX], s_diag[NBOX], s_idx[NBOX], s_flagg[NBOX];
    __shared__ unsigned s_candm[4], s_joinm[4];
    __shared__ int s_jointg[NBOX], s_addcnt[NBOX];
    __shared__ int s_aidx[NBOX * NANCH];
    // sample-phase shared state (per-class key arrays)
    __shared__ unsigned sk3[LCAP], sk2[2 * LCAP], sk1[3 * LCAP];
    __shared__ int sidx[NSAMP];
    __shared__ int s_n3, s_n2, s_n1;

    int tid = threadIdx.x, lane = tid & 31, w = tid >> 5;
    int g = blockIdx.x;

    // ================= group phase (redundant in every block) =================
    if (tid < NBOX) {
        s_lab[tid]  = labels[tid];
        s_diag[tid] = g_inter[tid * NBOX + tid];
        s_jointg[tid] = -1;
        s_addcnt[tid] = 0;
    }
    for (int t = tid; t < NBOX * NANCH; t += 1024) s_aidx[t] = -1;
    if (tid == 0) { s_n3 = 0; s_n2 = 0; s_n1 = 0; }
    __syncthreads();

    #pragma unroll
    for (int rr = 0; rr < 4; rr++) {
        int i = w * 4 + rr;
        int li = s_lab[i], ci = s_diag[i];
        float best = -1.f; int bidx = 0;
        #pragma unroll
        for (int jj = 0; jj < 4; jj++) {
            int j = lane + jj * 32;
            float v = 0.f;
            if (j != i && s_lab[j] == li) {
                int in_ = g_inter[i * NBOX + j];
                int un  = ci + s_diag[j] - in_;
                if (un > 0) v = __fdiv_rn((float)in_, (float)un);
            }
            if (v > best) { best = v; bidx = j; }
        }
        #pragma unroll
        for (int o = 16; o; o >>= 1) {
            float v2 = __shfl_down_sync(0xffffffffu, best, o);
            int  b2  = __shfl_down_sync(0xffffffffu, bidx, o);
            if (v2 > best || (v2 == best && b2 < bidx)) { best = v2; bidx = b2; }
        }
        if (lane == 0) { s_idx[i] = bidx; s_flagg[i] = (best > 0.5f) ? 1 : 0; }
    }
    __syncthreads();
    if (tid < NBOX) {
        unsigned m = __ballot_sync(0xffffffffu, s_flagg[tid]);
        if (lane == 0) s_candm[w] = m;
    }
    __syncthreads();

    if (tid == 0) {
        unsigned jm0 = 0, jm1 = 0, jm2 = 0, jm3 = 0;
        #pragma unroll
        for (int wi = 0; wi < 4; wi++) {
            unsigned bm = s_candm[wi];
            while (bm) {
                int b = __ffs(bm) - 1; bm &= bm - 1;
                int ii = wi * 32 + b;
                int j = s_idx[ii];
                int gj = -1;
                if (j < ii) {
                    int jt = s_jointg[j];
                    if (jt >= 0) gj = jt;
                    else {
                        int jw = j >> 5, jb2 = j & 31;
                        unsigned sel = (jw == 0) ? jm0 : (jw == 1) ? jm1 : (jw == 2) ? jm2 : jm3;
                        int jb = __popc(sel & ((jb2 == 0) ? 0u : (0xffffffffu >> (32 - jb2))));
                        if (jw > 0) jb += __popc(jm0);
                        if (jw > 1) jb += __popc(jm1);
                        if (jw > 2) jb += __popc(jm2);
                        gj = j - jb;       // leader j's group id
                    }
                }
                if (gj >= 0 && s_addcnt[gj] < 2) {   // gcnt[gj] = 1 + addcnt < 3
                    int ts = 1 + s_addcnt[gj];
                    s_addcnt[gj] = ts;
                    s_jointg[ii] = gj;
                    s_aidx[gj * NANCH + ts] = ii;
                    if (wi == 0) jm0 |= 1u << b;
                    else if (wi == 1) jm1 |= 1u << b;
                    else if (wi == 2) jm2 |= 1u << b;
                    else jm3 |= 1u << b;
                }
            }
        }
        s_joinm[0] = jm0; s_joinm[1] = jm1; s_joinm[2] = jm2; s_joinm[3] = jm3;
    }
    __syncthreads();

    if (tid < NBOX) {
        int ii = tid;
        unsigned jmw = s_joinm[ii >> 5];
        if (!((jmw >> (ii & 31)) & 1u)) {
            int b2 = ii & 31;
            int jb = __popc(jmw & ((b2 == 0) ? 0u : (0xffffffffu >> (32 - b2))));
            if (ii >= 32)  jb += __popc(s_joinm[0]);
            if (ii >= 64)  jb += __popc(s_joinm[1]);
            if (ii >= 96)  jb += __popc(s_joinm[2]);
            s_aidx[(ii - jb) * NANCH + 0] = ii;
        }
    }
    __syncthreads();
    if (g == 0 && write_anchor && tid < NBOX) {
        #pragma unroll
        for (int k = 0; k < NANCH; k++)
            out_anchor[tid * NANCH + k] = (float)s_aidx[tid * NANCH + k];
    }

    // ================= sample phase (own group) =================
    float* orow = out + (size_t)g * NSAMP * 5;
    int a[3];
    a[0] = s_aidx[g * NANCH + 0];
    a[1] = s_aidx[g * NANCH + 1];
    a[2] = s_aidx[g * NANCH + 2];
    if (a[0] < 0) {
        for (int k = tid; k < NSAMP * 5; k += 1024) orow[k] = 0.f;
        return;
    }
    int nv = (a[1] < 0) ? 1 : ((a[2] < 0) ? 2 : 3);

    for (int k = 0; k < nv; k++) {
        int cnt = g_cnt[a[k]];
        if (cnt > LCAP) cnt = LCAP;
        for (int e = tid; e < cnt; e += 1024) {
            int p = g_list[a[k]][e];
            uint4 mv = g_listm[a[k]][e];
            unsigned mm[4] = {mv.x, mv.y, mv.z, mv.w};
            bool dup = false;
            int cls = 1;
            #pragma unroll
            for (int j = 0; j < 3; j++) {
                if (j < nv && j != k) {
                    unsigned in = (mm[a[j] >> 5] >> (a[j] & 31)) & 1u;
                    if (in) { cls++; if (j < k) dup = true; }
                }
            }
            if (!dup) {
                if (cls == 3)      sk3[atomicAdd(&s_n3, 1)] = (unsigned)p;
                else if (cls == 2) sk2[atomicAdd(&s_n2, 1)] = (unsigned)p;
                else               sk1[atomicAdd(&s_n1, 1)] = (unsigned)p;
            }
        }
    }
    __syncthreads();
    int n3 = s_n3, n2 = s_n2, n1 = s_n1;

    // class 3 (base 0), class 2 (base n3), class 1 (base n3+n2); idx ascending
    for (int i = tid; i < n3; i += 1024) {
        unsigned my = sk3[i];
        int r = 0;
        for (int j = 0; j < n3; j++) r += (sk3[j] < my);
        if (r < NSAMP) sidx[r] = (int)my;
    }
    if (n3 < NSAMP) {
        for (int i = tid; i < n2; i += 1024) {
            unsigned my = sk2[i];
            int r = 0;
            for (int j = 0; j < n2; j++) r += (sk2[j] < my);
            int pos = n3 + r;
            if (pos < NSAMP) sidx[pos] = (int)my;
        }
    }
    if (n3 + n2 < NSAMP) {
        for (int i = tid; i < n1; i += 1024) {
            unsigned my = sk1[i];
            int r = 0;
            for (int j = 0; j < n1; j++) r += (sk1[j] < my);
            int pos = n3 + n2 + r;
            if (pos < NSAMP) sidx[pos] = (int)my;
        }
    }
    __syncthreads();
    int total = n3 + n2 + n1;
    int filled = total < NSAMP ? total : NSAMP;
    for (int k = tid; k < NSAMP * 5; k += 1024) {
        int s = k / 5, f = k - s * 5;
        orow[k] = (s < filled) ? pts[(size_t)sidx[s] * 5 + f] : 0.f;
    }
}

// ---------------------------------------------------------------------------
extern "C" void kernel_launch(void* const* d_in, const int* in_sizes, int n_in,
                              void* d_out, int out_size)
{
    const float* pts    = (const float*)d_in[0];
    const float* boxes  = (const float*)d_in[1];
    const int*   labels = (const int*)d_in[2];
    float* out = (float*)d_out;

    const int sampled_elems = NBOX * NSAMP * 5;
    int write_anchor = (out_size >= sampled_elems + NBOX * NANCH) ? 1 : 0;
    float* out_anchor = out + sampled_elems;

    k_setup<<<9, 1024>>>(boxes);
    k_points<<<(NPTS + 255) / 256, 256>>>(pts);
    k_tail<<<NBOX, 1024>>>(pts, labels, out, out_anchor, write_anchor);
}